// round 6
// baseline (speedup 1.0000x reference)
#include <cuda_runtime.h>

#define EPS 1e-6f

static constexpr int B_ = 64;
static constexpr int T_ = 8000;
static constexpr int M_ = 80;
static constexpr int MQ = M_ / 4;        // 20 float4 lanes per row
static constexpr int CL = 100;           // timesteps per block (chunk)
static constexpr int NC = T_ / CL;       // 80 chunks per batch row
static constexpr int SS = 10;            // subchunks per chunk
static constexpr int L  = CL / SS;       // 10 steps per subchunk
static constexpr int SCAN_T = MQ * SS;   // 200 scan/epilogue threads
static constexpr int NTHREADS = 256;

// Cross-block chain state (no cudaMalloc allowed).
__device__ float4 g_incl[B_ * MQ];       // per-lane inclusive carry, overwritten along the chain
__device__ int    g_flag[NC * B_];       // chunk (c,b) published?

// Single-instruction MUFU wrappers.
__device__ __forceinline__ float fast_lg2(float v) {
    float r; asm("lg2.approx.f32 %0, %1;" : "=f"(r) : "f"(v)); return r;
}
__device__ __forceinline__ float fast_ex2(float v) {
    float r; asm("ex2.approx.f32 %0, %1;" : "=f"(r) : "f"(v)); return r;
}

// out = (x*(m+eps)^(-alpha) + delta)^r - delta^r, division-free (4 MUFU ops)
__device__ __forceinline__ float pcen_out(float xv, float mv, float nalpha,
                                          float delta, float r, float dr) {
    float l   = fast_lg2(mv + EPS);
    float den = fast_ex2(nalpha * l);
    float y   = fmaf(xv, den, delta);
    return fast_ex2(r * fast_lg2(y)) - dr;
}

__global__ void pcen_init_flags() {
    int i = blockIdx.x * blockDim.x + threadIdx.x;
    if (i < NC * B_) g_flag[i] = 0;
}

// ---------------------------------------------------------------------------
// Fused chained-scan PCEN. Block bid = c*B_ + b (c-major: predecessors have
// strictly lower bid -> scheduled earlier -> spin is deadlock-free).
// Phases:
//  1. stage x tile [CL][MQ] float4 into SMEM (the ONLY DRAM read of x)
//  2. thread (mq,ss): local EMA over L steps (zero-init), endpoint -> sm_ep
//  3. threads mq<20: serial exclusive combine over SS endpoints (dL=oms^L);
//     spin on chunk c-1's flag, read its inclusive carry, publish own
//     inclusive (= local_end + oms^CL * carry), set flag
//  4. thread (mq,ss): m_in = p(ss) + oms^(ss*L)*carry; rescan L steps from
//     SMEM, epilogue, write out
// ---------------------------------------------------------------------------
__global__ void __launch_bounds__(NTHREADS) pcen_fused(
        const float4* __restrict__ x,
        const float* __restrict__ log_s,
        const float* __restrict__ log_alpha,
        const float* __restrict__ log_delta,
        const float* __restrict__ log_r,
        float4* __restrict__ out) {
    __shared__ float4 sm_tile[CL * MQ];   // 32000 B
    __shared__ float4 sm_ep[SS * MQ];     // endpoints -> exclusive carries
    __shared__ float4 sm_cb[MQ];          // block carry-in broadcast

    const int bid = blockIdx.x;
    const int c   = bid / B_;
    const int b   = bid % B_;
    const int tid = threadIdx.x;

    const float4* xp = x + ((size_t)b * T_ + (size_t)c * CL) * MQ;

    // Phase 1: cooperative contiguous tile load (32 KB, fully coalesced).
    for (int i = tid; i < CL * MQ; i += NTHREADS)
        sm_tile[i] = __ldg(xp + i);
    __syncthreads();

    const int mq = tid % MQ;
    const int ss = tid / MQ;

    float4 s4, o4;
    if (tid < SCAN_T) {
        int m0 = mq * 4;
        s4.x = __expf(log_s[m0 + 0]); s4.y = __expf(log_s[m0 + 1]);
        s4.z = __expf(log_s[m0 + 2]); s4.w = __expf(log_s[m0 + 3]);
        o4.x = 1.0f - s4.x; o4.y = 1.0f - s4.y;
        o4.z = 1.0f - s4.z; o4.w = 1.0f - s4.w;

        // Phase 2: zero-init local scan over this subchunk.
        float4 e = make_float4(0.f, 0.f, 0.f, 0.f);
#pragma unroll
        for (int j = 0; j < L; j++) {
            float4 xv = sm_tile[(ss * L + j) * MQ + mq];
            e.x = fmaf(o4.x, e.x, s4.x * xv.x);
            e.y = fmaf(o4.y, e.y, s4.y * xv.y);
            e.z = fmaf(o4.z, e.z, s4.z * xv.z);
            e.w = fmaf(o4.w, e.w, s4.w * xv.w);
        }
        sm_ep[ss * MQ + mq] = e;
    }
    __syncthreads();

    // Phase 3: in-block combine + cross-block chain (warp 0, lanes 0..19).
    if (tid < MQ) {
        float4 dL = make_float4(1.f, 1.f, 1.f, 1.f);
#pragma unroll
        for (int k = 0; k < L; k++) {
            dL.x *= o4.x; dL.y *= o4.y; dL.z *= o4.z; dL.w *= o4.w;
        }
        float4 dC = make_float4(1.f, 1.f, 1.f, 1.f);
#pragma unroll
        for (int k = 0; k < SS; k++) {
            dC.x *= dL.x; dC.y *= dL.y; dC.z *= dL.z; dC.w *= dL.w;
        }

        // Exclusive combine: sm_ep[ss] becomes carry-at-subchunk-start
        // (relative to zero block init); p ends as the block-local endpoint.
        float4 p = make_float4(0.f, 0.f, 0.f, 0.f);
#pragma unroll
        for (int k = 0; k < SS; k++) {
            float4 e = sm_ep[k * MQ + mq];
            sm_ep[k * MQ + mq] = p;
            p.x = fmaf(dL.x, p.x, e.x);
            p.y = fmaf(dL.y, p.y, e.y);
            p.z = fmaf(dL.z, p.z, e.z);
            p.w = fmaf(dL.w, p.w, e.w);
        }

        // Cross-block: wait for predecessor's inclusive carry.
        float4 cb = make_float4(0.f, 0.f, 0.f, 0.f);
        if (c > 0) {
            volatile int* f = &g_flag[(c - 1) * B_ + b];
            while (*f == 0) { __nanosleep(32); }
            __threadfence();
            volatile float* gi =
                reinterpret_cast<volatile float*>(&g_incl[b * MQ + mq]);
            cb.x = gi[0]; cb.y = gi[1]; cb.z = gi[2]; cb.w = gi[3];
        }
        sm_cb[mq] = cb;

        float4 incl;
        incl.x = fmaf(dC.x, cb.x, p.x);
        incl.y = fmaf(dC.y, cb.y, p.y);
        incl.z = fmaf(dC.z, cb.z, p.z);
        incl.w = fmaf(dC.w, cb.w, p.w);
        {
            volatile float* gi =
                reinterpret_cast<volatile float*>(&g_incl[b * MQ + mq]);
            gi[0] = incl.x; gi[1] = incl.y; gi[2] = incl.z; gi[3] = incl.w;
        }
        __threadfence();
        __syncwarp(0x000FFFFFu);
        if (tid == 0) {
            volatile int* f = &g_flag[c * B_ + b];
            *f = 1;
        }
    }
    __syncthreads();

    // Phase 4: exact-carry rescan + epilogue + store.
    if (tid < SCAN_T) {
        int m0 = mq * 4;
        float4 na, d4, r4, dr4;
        na.x = -__expf(log_alpha[m0 + 0]); na.y = -__expf(log_alpha[m0 + 1]);
        na.z = -__expf(log_alpha[m0 + 2]); na.w = -__expf(log_alpha[m0 + 3]);
        d4.x = __expf(log_delta[m0 + 0]); d4.y = __expf(log_delta[m0 + 1]);
        d4.z = __expf(log_delta[m0 + 2]); d4.w = __expf(log_delta[m0 + 3]);
        r4.x = __expf(log_r[m0 + 0]); r4.y = __expf(log_r[m0 + 1]);
        r4.z = __expf(log_r[m0 + 2]); r4.w = __expf(log_r[m0 + 3]);
        dr4.x = __expf(r4.x * log_delta[m0 + 0]);
        dr4.y = __expf(r4.y * log_delta[m0 + 1]);
        dr4.z = __expf(r4.z * log_delta[m0 + 2]);
        dr4.w = __expf(r4.w * log_delta[m0 + 3]);

        // dL = oms^L, f = dL^ss (decay from block start to subchunk start)
        float4 dL = make_float4(1.f, 1.f, 1.f, 1.f);
#pragma unroll
        for (int k = 0; k < L; k++) {
            dL.x *= o4.x; dL.y *= o4.y; dL.z *= o4.z; dL.w *= o4.w;
        }
        float4 f = make_float4(1.f, 1.f, 1.f, 1.f);
        for (int k = 0; k < ss; k++) {
            f.x *= dL.x; f.y *= dL.y; f.z *= dL.z; f.w *= dL.w;
        }

        float4 cb = sm_cb[mq];
        float4 m  = sm_ep[ss * MQ + mq];   // zero-init carry at subchunk start
        m.x = fmaf(f.x, cb.x, m.x);
        m.y = fmaf(f.y, cb.y, m.y);
        m.z = fmaf(f.z, cb.z, m.z);
        m.w = fmaf(f.w, cb.w, m.w);

        float4* op = out + ((size_t)b * T_ + (size_t)c * CL) * MQ;
#pragma unroll
        for (int j = 0; j < L; j++) {
            float4 xv = sm_tile[(ss * L + j) * MQ + mq];
            m.x = fmaf(o4.x, m.x, s4.x * xv.x);
            m.y = fmaf(o4.y, m.y, s4.y * xv.y);
            m.z = fmaf(o4.z, m.z, s4.z * xv.z);
            m.w = fmaf(o4.w, m.w, s4.w * xv.w);
            float4 ov;
            ov.x = pcen_out(xv.x, m.x, na.x, d4.x, r4.x, dr4.x);
            ov.y = pcen_out(xv.y, m.y, na.y, d4.y, r4.y, dr4.y);
            ov.z = pcen_out(xv.z, m.z, na.z, d4.z, r4.z, dr4.z);
            ov.w = pcen_out(xv.w, m.w, na.w, d4.w, r4.w, dr4.w);
            op[(ss * L + j) * MQ + mq] = ov;
        }
    }
}

extern "C" void kernel_launch(void* const* d_in, const int* in_sizes, int n_in,
                              void* d_out, int out_size) {
    const float* x         = (const float*)d_in[0];
    const float* log_s     = (const float*)d_in[1];
    const float* log_alpha = (const float*)d_in[2];
    const float* log_delta = (const float*)d_in[3];
    const float* log_r     = (const float*)d_in[4];
    float* out = (float*)d_out;

    pcen_init_flags<<<(NC * B_ + 255) / 256, 256>>>();
    pcen_fused<<<NC * B_, NTHREADS>>>(
        (const float4*)x, log_s, log_alpha, log_delta, log_r, (float4*)out);
}

// round 7
// speedup vs baseline: 1.2628x; 1.2628x over previous
#include <cuda_runtime.h>

#define EPS 1e-6f

static constexpr int B_ = 64;
static constexpr int T_ = 8000;
static constexpr int M_ = 80;
static constexpr int MQ = M_ / 4;        // 20 float4 lanes per row
static constexpr int CL = 100;           // timesteps per block (chunk)
static constexpr int NC = T_ / CL;       // 80 chunks per batch row
static constexpr int SS = 10;            // subchunks per chunk
static constexpr int L  = CL / SS;       // 10 steps per subchunk
static constexpr int SCAN_T = MQ * SS;   // 200 scan/epilogue threads
static constexpr int NTHREADS = 256;

// Cross-block state (no cudaMalloc allowed).
// g_part[c][b][mq]: block-local zero-init EMA endpoint (published early,
// NO cross-block dependency -> no serial chain).
__device__ float4 g_part[NC * B_ * MQ];  // 1.6 MB, L2-resident
__device__ int    g_flag[NC * B_];

// Single-instruction MUFU wrappers.
__device__ __forceinline__ float fast_lg2(float v) {
    float r; asm("lg2.approx.f32 %0, %1;" : "=f"(r) : "f"(v)); return r;
}
__device__ __forceinline__ float fast_ex2(float v) {
    float r; asm("ex2.approx.f32 %0, %1;" : "=f"(r) : "f"(v)); return r;
}

// out = (x*(m+eps)^(-alpha) + delta)^r - delta^r, division-free (4 MUFU ops)
__device__ __forceinline__ float pcen_out(float xv, float mv, float nalpha,
                                          float delta, float r, float dr) {
    float l   = fast_lg2(mv + EPS);
    float den = fast_ex2(nalpha * l);
    float y   = fmaf(xv, den, delta);
    return fast_ex2(r * fast_lg2(y)) - dr;
}

__global__ void pcen_init_flags() {
    int i = blockIdx.x * blockDim.x + threadIdx.x;
    if (i < NC * B_) g_flag[i] = 0;
}

// ---------------------------------------------------------------------------
// Fused decoupled-lookback PCEN. Block bid = c*B_ + b (c-major; waits only on
// lower bids -> deadlock-free).
//  1. stage x tile [CL][MQ] float4 in SMEM (the ONLY DRAM read of x)
//  2. thread (mq,ss): zero-init local EMA over its L steps -> sm_ep
//  3a. lanes mq<20: exclusive combine of SS endpoints (sm_ep := subchunk
//      carry-at-start rel. zero block init); publish block partial to L2
//      (__stcg) + release flag   <-- no dependency on other blocks
//  3b. thread i<c spins on flag i; acquire fence
//  3c. lanes mq<20: carry-in = fmaf-chain over predecessors' partials
//      (__ldcg, independent addresses -> MLP) -> sm_cb
//  4. thread (mq,ss): m_in = sm_ep + dL^ss * carry; rescan + epilogue + store
// ---------------------------------------------------------------------------
__global__ void __launch_bounds__(NTHREADS) pcen_fused(
        const float4* __restrict__ x,
        const float* __restrict__ log_s,
        const float* __restrict__ log_alpha,
        const float* __restrict__ log_delta,
        const float* __restrict__ log_r,
        float4* __restrict__ out) {
    __shared__ float4 sm_tile[CL * MQ];   // 32000 B
    __shared__ float4 sm_ep[SS * MQ];
    __shared__ float4 sm_cb[MQ];

    const int bid = blockIdx.x;
    const int c   = bid / B_;
    const int b   = bid % B_;
    const int tid = threadIdx.x;

    const float4* xp = x + ((size_t)b * T_ + (size_t)c * CL) * MQ;

    // Phase 1: cooperative contiguous tile load (32 KB, fully coalesced).
    for (int i = tid; i < CL * MQ; i += NTHREADS)
        sm_tile[i] = __ldg(xp + i);
    __syncthreads();

    const int mq = tid % MQ;
    const int ss = tid / MQ;

    float4 s4, o4;
    if (tid < SCAN_T) {
        int m0 = mq * 4;
        s4.x = __expf(log_s[m0 + 0]); s4.y = __expf(log_s[m0 + 1]);
        s4.z = __expf(log_s[m0 + 2]); s4.w = __expf(log_s[m0 + 3]);
        o4.x = 1.0f - s4.x; o4.y = 1.0f - s4.y;
        o4.z = 1.0f - s4.z; o4.w = 1.0f - s4.w;

        // Phase 2: zero-init local scan over this subchunk.
        float4 e = make_float4(0.f, 0.f, 0.f, 0.f);
#pragma unroll
        for (int j = 0; j < L; j++) {
            float4 xv = sm_tile[(ss * L + j) * MQ + mq];
            e.x = fmaf(o4.x, e.x, s4.x * xv.x);
            e.y = fmaf(o4.y, e.y, s4.y * xv.y);
            e.z = fmaf(o4.z, e.z, s4.z * xv.z);
            e.w = fmaf(o4.w, e.w, s4.w * xv.w);
        }
        sm_ep[ss * MQ + mq] = e;
    }
    __syncthreads();

    float4 dL, dC;
    if (tid < MQ) {
        // Phase 3a: in-block exclusive combine + EARLY partial publish.
        dL = make_float4(1.f, 1.f, 1.f, 1.f);
#pragma unroll
        for (int k = 0; k < L; k++) {
            dL.x *= o4.x; dL.y *= o4.y; dL.z *= o4.z; dL.w *= o4.w;
        }
        dC = make_float4(1.f, 1.f, 1.f, 1.f);
#pragma unroll
        for (int k = 0; k < SS; k++) {
            dC.x *= dL.x; dC.y *= dL.y; dC.z *= dL.z; dC.w *= dL.w;
        }

        float4 p = make_float4(0.f, 0.f, 0.f, 0.f);
#pragma unroll
        for (int k = 0; k < SS; k++) {
            float4 e = sm_ep[k * MQ + mq];
            sm_ep[k * MQ + mq] = p;
            p.x = fmaf(dL.x, p.x, e.x);
            p.y = fmaf(dL.y, p.y, e.y);
            p.z = fmaf(dL.z, p.z, e.z);
            p.w = fmaf(dL.w, p.w, e.w);
        }
        __stcg(&g_part[((size_t)c * B_ + b) * MQ + mq], p);
        __syncwarp(0x000FFFFFu);
        if (tid == 0) {
            __threadfence();
            volatile int* f = &g_flag[c * B_ + b];
            *f = 1;
        }
    }

    // Phase 3b: parallel wait for ALL predecessor partials (thread i <-> c-1
    // chunks; each spins on its own flag). Partials have no cross-block
    // dependency, so these flags are set wave-concurrently, not serially.
    if (tid < c) {
        volatile int* f = &g_flag[tid * B_ + b];
        while (*f == 0) { __nanosleep(32); }
        __threadfence();   // acquire
    }
    __syncthreads();

    // Phase 3c: redundant carry-in combine (same fmaf recurrence as a serial
    // inclusive chain -> identical rounding to the R3 scheme).
    if (tid < MQ) {
        float4 carry = make_float4(0.f, 0.f, 0.f, 0.f);
        const float4* gp = &g_part[(size_t)b * MQ + mq];
#pragma unroll 4
        for (int k = 0; k < c; k++) {
            float4 p = __ldcg(gp + (size_t)k * (B_ * MQ));
            carry.x = fmaf(dC.x, carry.x, p.x);
            carry.y = fmaf(dC.y, carry.y, p.y);
            carry.z = fmaf(dC.z, carry.z, p.z);
            carry.w = fmaf(dC.w, carry.w, p.w);
        }
        sm_cb[mq] = carry;
    }
    __syncthreads();

    // Phase 4: exact-carry rescan + epilogue + store.
    if (tid < SCAN_T) {
        int m0 = mq * 4;
        float4 na, d4, r4, dr4;
        na.x = -__expf(log_alpha[m0 + 0]); na.y = -__expf(log_alpha[m0 + 1]);
        na.z = -__expf(log_alpha[m0 + 2]); na.w = -__expf(log_alpha[m0 + 3]);
        d4.x = __expf(log_delta[m0 + 0]); d4.y = __expf(log_delta[m0 + 1]);
        d4.z = __expf(log_delta[m0 + 2]); d4.w = __expf(log_delta[m0 + 3]);
        r4.x = __expf(log_r[m0 + 0]); r4.y = __expf(log_r[m0 + 1]);
        r4.z = __expf(log_r[m0 + 2]); r4.w = __expf(log_r[m0 + 3]);
        dr4.x = __expf(r4.x * log_delta[m0 + 0]);
        dr4.y = __expf(r4.y * log_delta[m0 + 1]);
        dr4.z = __expf(r4.z * log_delta[m0 + 2]);
        dr4.w = __expf(r4.w * log_delta[m0 + 3]);

        float4 dLl = make_float4(1.f, 1.f, 1.f, 1.f);
#pragma unroll
        for (int k = 0; k < L; k++) {
            dLl.x *= o4.x; dLl.y *= o4.y; dLl.z *= o4.z; dLl.w *= o4.w;
        }
        float4 f = make_float4(1.f, 1.f, 1.f, 1.f);
        for (int k = 0; k < ss; k++) {
            f.x *= dLl.x; f.y *= dLl.y; f.z *= dLl.z; f.w *= dLl.w;
        }

        float4 cb = sm_cb[mq];
        float4 m  = sm_ep[ss * MQ + mq];
        m.x = fmaf(f.x, cb.x, m.x);
        m.y = fmaf(f.y, cb.y, m.y);
        m.z = fmaf(f.z, cb.z, m.z);
        m.w = fmaf(f.w, cb.w, m.w);

        float4* op = out + ((size_t)b * T_ + (size_t)c * CL) * MQ;
#pragma unroll
        for (int j = 0; j < L; j++) {
            float4 xv = sm_tile[(ss * L + j) * MQ + mq];
            m.x = fmaf(o4.x, m.x, s4.x * xv.x);
            m.y = fmaf(o4.y, m.y, s4.y * xv.y);
            m.z = fmaf(o4.z, m.z, s4.z * xv.z);
            m.w = fmaf(o4.w, m.w, s4.w * xv.w);
            float4 ov;
            ov.x = pcen_out(xv.x, m.x, na.x, d4.x, r4.x, dr4.x);
            ov.y = pcen_out(xv.y, m.y, na.y, d4.y, r4.y, dr4.y);
            ov.z = pcen_out(xv.z, m.z, na.z, d4.z, r4.z, dr4.z);
            ov.w = pcen_out(xv.w, m.w, na.w, d4.w, r4.w, dr4.w);
            op[(ss * L + j) * MQ + mq] = ov;
        }
    }
}

extern "C" void kernel_launch(void* const* d_in, const int* in_sizes, int n_in,
                              void* d_out, int out_size) {
    const float* x         = (const float*)d_in[0];
    const float* log_s     = (const float*)d_in[1];
    const float* log_alpha = (const float*)d_in[2];
    const float* log_delta = (const float*)d_in[3];
    const float* log_r     = (const float*)d_in[4];
    float* out = (float*)d_out;

    pcen_init_flags<<<(NC * B_ + 255) / 256, 256>>>();
    pcen_fused<<<NC * B_, NTHREADS>>>(
        (const float4*)x, log_s, log_alpha, log_delta, log_r, (float4*)out);
}

// round 8
// speedup vs baseline: 1.3987x; 1.1077x over previous
#include <cuda_runtime.h>

#define EPS 1e-6f

static constexpr int B_ = 64;
static constexpr int T_ = 8000;
static constexpr int M_ = 80;
static constexpr int MQ = M_ / 4;        // 20 float4 lanes per row
static constexpr int CL = 125;           // timesteps per block (chunk)
static constexpr int NC = T_ / CL;       // 64 chunks per batch row
static constexpr int SS = 25;            // subchunks per chunk
static constexpr int L  = CL / SS;       // 5 steps per subchunk
static constexpr int SCAN_T = MQ * SS;   // 500 active threads
static constexpr int NTHREADS = 512;

// Cross-block state (no cudaMalloc allowed).
// g_part[c][b][mq]: block-local zero-init EMA endpoint (no cross-block dep).
__device__ float4 g_part[NC * B_ * MQ];  // 1.3 MB, L2-resident
__device__ int    g_flag[NC * B_];

// Single-instruction MUFU wrappers.
__device__ __forceinline__ float fast_lg2(float v) {
    float r; asm("lg2.approx.f32 %0, %1;" : "=f"(r) : "f"(v)); return r;
}
__device__ __forceinline__ float fast_ex2(float v) {
    float r; asm("ex2.approx.f32 %0, %1;" : "=f"(r) : "f"(v)); return r;
}

// out = (x*(m+eps)^(-alpha) + delta)^r - delta^r, division-free (4 MUFU ops)
__device__ __forceinline__ float pcen_out(float xv, float mv, float nalpha,
                                          float delta, float r, float dr) {
    float l   = fast_lg2(mv + EPS);
    float den = fast_ex2(nalpha * l);
    float y   = fmaf(xv, den, delta);
    return fast_ex2(r * fast_lg2(y)) - dr;
}

__global__ void pcen_init_flags() {
    int i = blockIdx.x * blockDim.x + threadIdx.x;
    if (i < NC * B_) g_flag[i] = 0;
}

// ---------------------------------------------------------------------------
// Fused decoupled-lookback PCEN, register-resident x.
// Block bid = c*B_ + b (c-major; waits only on lower bids -> deadlock-free).
//  2.  thread (mq,ss): load its L float4 x-values ONCE into registers,
//      zero-init local EMA -> sm_ep
//  3a. lanes mq<20: exclusive combine of SS endpoints; publish block partial
//      (__stcg) + release flag (no dependency on other blocks)
//  3b. thread i<c spins on flag i (parallel); acquire; __syncthreads
//  3c. ALL threads cooperatively stage predecessor partials into SMEM
//      (<=1260 float4, one pipelined L2 round trip); 20 lanes then run the
//      serial fmaf chain from SMEM at FMA latency
//  4.  thread (mq,ss): m_in = sm_ep + dL^ss * carry; rescan from REGISTERS,
//      epilogue, store out
// ---------------------------------------------------------------------------
__global__ void __launch_bounds__(NTHREADS, 2) pcen_fused(
        const float4* __restrict__ x,
        const float* __restrict__ log_s,
        const float* __restrict__ log_alpha,
        const float* __restrict__ log_delta,
        const float* __restrict__ log_r,
        float4* __restrict__ out) {
    __shared__ float4 sm_ep[SS * MQ];        // 8000 B
    __shared__ float4 sm_lb[(NC - 1) * MQ];  // 20160 B lookback staging
    __shared__ float4 sm_cb[MQ];             // carry broadcast

    const int bid = blockIdx.x;
    const int c   = bid / B_;
    const int b   = bid % B_;
    const int tid = threadIdx.x;
    const int mq  = tid % MQ;
    const int ss  = tid / MQ;
    const bool active = (tid < SCAN_T);

    const float4* xp = x + ((size_t)b * T_ + (size_t)c * CL) * MQ;

    float4 xv[L];
    float4 s4, o4;
    if (active) {
        int m0 = mq * 4;
        s4.x = __expf(log_s[m0 + 0]); s4.y = __expf(log_s[m0 + 1]);
        s4.z = __expf(log_s[m0 + 2]); s4.w = __expf(log_s[m0 + 3]);
        o4.x = 1.0f - s4.x; o4.y = 1.0f - s4.y;
        o4.z = 1.0f - s4.z; o4.w = 1.0f - s4.w;

        // Phase 2: the ONLY read of x; values stay in registers.
        float4 e = make_float4(0.f, 0.f, 0.f, 0.f);
#pragma unroll
        for (int j = 0; j < L; j++) {
            xv[j] = __ldg(xp + (ss * L + j) * MQ + mq);
            e.x = fmaf(o4.x, e.x, s4.x * xv[j].x);
            e.y = fmaf(o4.y, e.y, s4.y * xv[j].y);
            e.z = fmaf(o4.z, e.z, s4.z * xv[j].z);
            e.w = fmaf(o4.w, e.w, s4.w * xv[j].w);
        }
        sm_ep[ss * MQ + mq] = e;
    }
    __syncthreads();

    float4 dC;
    if (tid < MQ) {
        // Phase 3a: in-block exclusive combine + EARLY partial publish.
        float4 dL = make_float4(1.f, 1.f, 1.f, 1.f);
#pragma unroll
        for (int k = 0; k < L; k++) {
            dL.x *= o4.x; dL.y *= o4.y; dL.z *= o4.z; dL.w *= o4.w;
        }
        dC = make_float4(1.f, 1.f, 1.f, 1.f);
#pragma unroll
        for (int k = 0; k < SS; k++) {
            dC.x *= dL.x; dC.y *= dL.y; dC.z *= dL.z; dC.w *= dL.w;
        }

        float4 p = make_float4(0.f, 0.f, 0.f, 0.f);
#pragma unroll 5
        for (int k = 0; k < SS; k++) {
            float4 e = sm_ep[k * MQ + mq];
            sm_ep[k * MQ + mq] = p;
            p.x = fmaf(dL.x, p.x, e.x);
            p.y = fmaf(dL.y, p.y, e.y);
            p.z = fmaf(dL.z, p.z, e.z);
            p.w = fmaf(dL.w, p.w, e.w);
        }
        __stcg(&g_part[((size_t)c * B_ + b) * MQ + mq], p);
        __syncwarp(0x000FFFFFu);
        if (tid == 0) {
            __threadfence();
            *(volatile int*)&g_flag[c * B_ + b] = 1;
        }
    }

    // Phase 3b: parallel wait for all predecessor partials.
    if (tid < c) {
        volatile int* f = &g_flag[tid * B_ + b];
        while (*f == 0) { __nanosleep(32); }
        __threadfence();   // acquire
    }
    __syncthreads();

    // Phase 3c: cooperative staging of predecessor partials (high MLP), then
    // short serial chain from SMEM (same fmaf order as a serial scan).
    for (int i = tid; i < c * MQ; i += NTHREADS) {
        int k = i / MQ, l = i % MQ;
        sm_lb[i] = __ldcg(&g_part[((size_t)k * B_ + b) * MQ + l]);
    }
    __syncthreads();

    if (tid < MQ) {
        float4 carry = make_float4(0.f, 0.f, 0.f, 0.f);
        for (int k = 0; k < c; k++) {
            float4 p = sm_lb[k * MQ + mq];
            carry.x = fmaf(dC.x, carry.x, p.x);
            carry.y = fmaf(dC.y, carry.y, p.y);
            carry.z = fmaf(dC.z, carry.z, p.z);
            carry.w = fmaf(dC.w, carry.w, p.w);
        }
        sm_cb[mq] = carry;
    }
    __syncthreads();

    // Phase 4: exact-carry rescan from registers + epilogue + store.
    if (active) {
        int m0 = mq * 4;
        float4 na, d4, r4, dr4;
        na.x = -__expf(log_alpha[m0 + 0]); na.y = -__expf(log_alpha[m0 + 1]);
        na.z = -__expf(log_alpha[m0 + 2]); na.w = -__expf(log_alpha[m0 + 3]);
        d4.x = __expf(log_delta[m0 + 0]); d4.y = __expf(log_delta[m0 + 1]);
        d4.z = __expf(log_delta[m0 + 2]); d4.w = __expf(log_delta[m0 + 3]);
        r4.x = __expf(log_r[m0 + 0]); r4.y = __expf(log_r[m0 + 1]);
        r4.z = __expf(log_r[m0 + 2]); r4.w = __expf(log_r[m0 + 3]);
        dr4.x = __expf(r4.x * log_delta[m0 + 0]);
        dr4.y = __expf(r4.y * log_delta[m0 + 1]);
        dr4.z = __expf(r4.z * log_delta[m0 + 2]);
        dr4.w = __expf(r4.w * log_delta[m0 + 3]);

        float4 dL = make_float4(1.f, 1.f, 1.f, 1.f);
#pragma unroll
        for (int k = 0; k < L; k++) {
            dL.x *= o4.x; dL.y *= o4.y; dL.z *= o4.z; dL.w *= o4.w;
        }
        float4 f = make_float4(1.f, 1.f, 1.f, 1.f);
        for (int k = 0; k < ss; k++) {
            f.x *= dL.x; f.y *= dL.y; f.z *= dL.z; f.w *= dL.w;
        }

        float4 cb = sm_cb[mq];
        float4 m  = sm_ep[ss * MQ + mq];   // zero-init carry at subchunk start
        m.x = fmaf(f.x, cb.x, m.x);
        m.y = fmaf(f.y, cb.y, m.y);
        m.z = fmaf(f.z, cb.z, m.z);
        m.w = fmaf(f.w, cb.w, m.w);

        float4* op = out + ((size_t)b * T_ + (size_t)c * CL) * MQ;
#pragma unroll
        for (int j = 0; j < L; j++) {
            m.x = fmaf(o4.x, m.x, s4.x * xv[j].x);
            m.y = fmaf(o4.y, m.y, s4.y * xv[j].y);
            m.z = fmaf(o4.z, m.z, s4.z * xv[j].z);
            m.w = fmaf(o4.w, m.w, s4.w * xv[j].w);
            float4 ov;
            ov.x = pcen_out(xv[j].x, m.x, na.x, d4.x, r4.x, dr4.x);
            ov.y = pcen_out(xv[j].y, m.y, na.y, d4.y, r4.y, dr4.y);
            ov.z = pcen_out(xv[j].z, m.z, na.z, d4.z, r4.z, dr4.z);
            ov.w = pcen_out(xv[j].w, m.w, na.w, d4.w, r4.w, dr4.w);
            op[(ss * L + j) * MQ + mq] = ov;
        }
    }
}

extern "C" void kernel_launch(void* const* d_in, const int* in_sizes, int n_in,
                              void* d_out, int out_size) {
    const float* x         = (const float*)d_in[0];
    const float* log_s     = (const float*)d_in[1];
    const float* log_alpha = (const float*)d_in[2];
    const float* log_delta = (const float*)d_in[3];
    const float* log_r     = (const float*)d_in[4];
    float* out = (float*)d_out;

    pcen_init_flags<<<(NC * B_ + 255) / 256, 256>>>();
    pcen_fused<<<NC * B_, NTHREADS>>>(
        (const float4*)x, log_s, log_alpha, log_delta, log_r, (float4*)out);
}